// round 10
// baseline (speedup 1.0000x reference)
#include <cuda_runtime.h>
#include <math.h>

#define BATCH  2
#define SEQ    2048
#define DMODEL 1024
#define NHEAD  16
#define DKH    64
#define MROWS  (BATCH * SEQ)          // 4096

// Scratch (static device globals: allocation-free, allowed by harness rules).
// NOTE: these must only ever be referenced from DEVICE code. Passing them as
// kernel arguments from host code yields the host shadow address (silently
// writable on GB300 via ATS!) — that was the round-3/4 bug.
__device__ float g_Qh[BATCH * NHEAD * SEQ * DKH];
__device__ float g_Kh[BATCH * NHEAD * SEQ * DKH];
__device__ float g_Vh[BATCH * NHEAD * SEQ * DKH];
__device__ float g_ctx[BATCH * NHEAD * SEQ * DKH];

// ---------------------------------------------------------------------------
// Projection GEMM: out_headsplit[b,h,s,dk] = (X @ W + bias)
// X: [MROWS, DMODEL] row-major. W: [DMODEL, DMODEL]. 64x64 tile, BK=16,
// 256 threads, 4x4 micro-tile per thread. N-tile of 64 == exactly one head.
// dst: 0 -> g_Qh, 1 -> g_Kh, 2 -> g_Vh  (resolved in device code!)
// ---------------------------------------------------------------------------
__global__ __launch_bounds__(256) void proj_kernel(
    const float* __restrict__ X, const float* __restrict__ W,
    const float* __restrict__ bias, int dst)
{
    float* out = (dst == 0) ? g_Qh : (dst == 1) ? g_Kh : g_Vh;

    __shared__ float As[16][64];   // [k][m]  (transposed A tile)
    __shared__ float Bs[16][64];   // [k][n]

    const int n0 = blockIdx.x * 64;
    const int m0 = blockIdx.y * 64;
    const int tid = threadIdx.x;
    const int tx = tid & 15, ty = tid >> 4;

    float acc[4][4] = {};

    for (int k0 = 0; k0 < DMODEL; k0 += 16) {
        {   // A tile: 64 rows x 16 k, one float4 per thread
            int row = tid >> 2;
            int kq  = (tid & 3) * 4;
            float4 a = *(const float4*)&X[(size_t)(m0 + row) * DMODEL + k0 + kq];
            As[kq + 0][row] = a.x; As[kq + 1][row] = a.y;
            As[kq + 2][row] = a.z; As[kq + 3][row] = a.w;
        }
        {   // B tile: 16 rows x 64 n, one float4 per thread
            int row = tid >> 4;
            int nq  = (tid & 15) * 4;
            *(float4*)&Bs[row][nq] =
                *(const float4*)&W[(size_t)(k0 + row) * DMODEL + n0 + nq];
        }
        __syncthreads();
        #pragma unroll
        for (int k = 0; k < 16; k++) {
            float a[4], b[4];
            #pragma unroll
            for (int i = 0; i < 4; i++) a[i] = As[k][ty * 4 + i];
            #pragma unroll
            for (int j = 0; j < 4; j++) b[j] = Bs[k][tx * 4 + j];
            #pragma unroll
            for (int i = 0; i < 4; i++)
                #pragma unroll
                for (int j = 0; j < 4; j++)
                    acc[i][j] = fmaf(a[i], b[j], acc[i][j]);
        }
        __syncthreads();
    }

    const int h = n0 / DKH;   // one head per N-tile
    #pragma unroll
    for (int i = 0; i < 4; i++) {
        int m = m0 + ty * 4 + i;
        int b = m / SEQ, s = m % SEQ;
        size_t base = ((size_t)(b * NHEAD + h) * SEQ + s) * DKH;
        #pragma unroll
        for (int j = 0; j < 4; j++) {
            int dk = tx * 4 + j;
            out[base + dk] = acc[i][j] + bias[n0 + dk];
        }
    }
}

// ---------------------------------------------------------------------------
// Scores: attn[bh, i, j] = (Qh[bh,i,:] . Kh[bh,j,:]) / 8
// Per block: 64x64 output tile, full K=64 reduction in one shot.
// ---------------------------------------------------------------------------
__global__ __launch_bounds__(256) void scores_kernel(float* __restrict__ attn)
{
    __shared__ float Qs[64][65];   // [m][k], padded
    __shared__ float Ks[64][65];   // [n][k], padded

    const int bh = blockIdx.z;
    const int n0 = blockIdx.x * 64;
    const int m0 = blockIdx.y * 64;
    const float* Q  = g_Qh + (size_t)bh * SEQ * DKH;
    const float* Kp = g_Kh + (size_t)bh * SEQ * DKH;
    const int tid = threadIdx.x;

    #pragma unroll
    for (int r = 0; r < 4; r++) {
        int row = (tid >> 4) + r * 16;       // 0..63
        int kq  = (tid & 15) * 4;
        float4 qv = *(const float4*)&Q [(size_t)(m0 + row) * DKH + kq];
        float4 kv = *(const float4*)&Kp[(size_t)(n0 + row) * DKH + kq];
        Qs[row][kq + 0] = qv.x; Qs[row][kq + 1] = qv.y;
        Qs[row][kq + 2] = qv.z; Qs[row][kq + 3] = qv.w;
        Ks[row][kq + 0] = kv.x; Ks[row][kq + 1] = kv.y;
        Ks[row][kq + 2] = kv.z; Ks[row][kq + 3] = kv.w;
    }
    __syncthreads();

    const int tx = tid & 15, ty = tid >> 4;
    float acc[4][4] = {};
    #pragma unroll
    for (int k = 0; k < 64; k++) {
        float a[4], b[4];
        #pragma unroll
        for (int i = 0; i < 4; i++) a[i] = Qs[ty * 4 + i][k];
        #pragma unroll
        for (int j = 0; j < 4; j++) b[j] = Ks[tx * 4 + j][k];
        #pragma unroll
        for (int i = 0; i < 4; i++)
            #pragma unroll
            for (int j = 0; j < 4; j++)
                acc[i][j] = fmaf(a[i], b[j], acc[i][j]);
    }

    #pragma unroll
    for (int i = 0; i < 4; i++) {
        size_t rowbase = ((size_t)bh * SEQ + (m0 + ty * 4 + i)) * SEQ + n0;
        #pragma unroll
        for (int j = 0; j < 4; j++)
            attn[rowbase + tx * 4 + j] = acc[i][j] * 0.125f;
    }
}

// ---------------------------------------------------------------------------
// Row softmax over 2048 elements, one block (256 threads) per row, in place.
// ---------------------------------------------------------------------------
__global__ __launch_bounds__(256) void softmax_kernel(float* __restrict__ attn)
{
    __shared__ float red[8];
    float* p = attn + (size_t)blockIdx.x * SEQ;
    const int tid  = threadIdx.x;
    const int lane = tid & 31, warp = tid >> 5;

    float4 v0 = ((const float4*)p)[tid];
    float4 v1 = ((const float4*)p)[tid + 256];

    float mx = fmaxf(fmaxf(fmaxf(v0.x, v0.y), fmaxf(v0.z, v0.w)),
                     fmaxf(fmaxf(v1.x, v1.y), fmaxf(v1.z, v1.w)));
    #pragma unroll
    for (int o = 16; o; o >>= 1) mx = fmaxf(mx, __shfl_xor_sync(0xffffffffu, mx, o));
    if (lane == 0) red[warp] = mx;
    __syncthreads();
    mx = red[0];
    #pragma unroll
    for (int w = 1; w < 8; w++) mx = fmaxf(mx, red[w]);
    __syncthreads();

    v0.x = __expf(v0.x - mx); v0.y = __expf(v0.y - mx);
    v0.z = __expf(v0.z - mx); v0.w = __expf(v0.w - mx);
    v1.x = __expf(v1.x - mx); v1.y = __expf(v1.y - mx);
    v1.z = __expf(v1.z - mx); v1.w = __expf(v1.w - mx);

    float sum = (v0.x + v0.y + v0.z + v0.w) + (v1.x + v1.y + v1.z + v1.w);
    #pragma unroll
    for (int o = 16; o; o >>= 1) sum += __shfl_xor_sync(0xffffffffu, sum, o);
    if (lane == 0) red[warp] = sum;
    __syncthreads();
    sum = red[0];
    #pragma unroll
    for (int w = 1; w < 8; w++) sum += red[w];

    float inv = 1.0f / sum;
    v0.x *= inv; v0.y *= inv; v0.z *= inv; v0.w *= inv;
    v1.x *= inv; v1.y *= inv; v1.z *= inv; v1.w *= inv;
    ((float4*)p)[tid]       = v0;
    ((float4*)p)[tid + 256] = v1;
}

// ---------------------------------------------------------------------------
// Context: g_ctx[bh, m, n] = sum_k attn[bh, m, k] * Vh[bh, k, n]
// M=2048, K=2048, N=64 per (b,h). 64x64 tile (full N), BK=32.
// ---------------------------------------------------------------------------
__global__ __launch_bounds__(256) void ctx_kernel(const float* __restrict__ attn)
{
    __shared__ float As[64][33];   // [m][k], padded
    __shared__ float Bs[32][64];   // [k][n]

    const int bh = blockIdx.y;
    const int m0 = blockIdx.x * 64;
    const float* V = g_Vh + (size_t)bh * SEQ * DKH;
    const float* A = attn + ((size_t)bh * SEQ + m0) * SEQ;
    const int tid = threadIdx.x;
    const int tx = tid & 15, ty = tid >> 4;

    float acc[4][4] = {};

    for (int k0 = 0; k0 < SEQ; k0 += 32) {
        #pragma unroll
        for (int r = 0; r < 2; r++) {      // A tile: 64x32, 2 float4 / thread
            int row = (tid >> 3) + r * 32;
            int kq  = (tid & 7) * 4;
            float4 a = *(const float4*)&A[(size_t)row * SEQ + k0 + kq];
            As[row][kq + 0] = a.x; As[row][kq + 1] = a.y;
            As[row][kq + 2] = a.z; As[row][kq + 3] = a.w;
        }
        #pragma unroll
        for (int r = 0; r < 2; r++) {      // B tile: 32x64, 2 float4 / thread
            int row = (tid >> 4) + r * 16;
            int nq  = (tid & 15) * 4;
            *(float4*)&Bs[row][nq] =
                *(const float4*)&V[(size_t)(k0 + row) * DKH + nq];
        }
        __syncthreads();
        #pragma unroll
        for (int k = 0; k < 32; k++) {
            float a[4], b[4];
            #pragma unroll
            for (int i = 0; i < 4; i++) a[i] = As[ty * 4 + i][k];
            #pragma unroll
            for (int j = 0; j < 4; j++) b[j] = Bs[k][tx * 4 + j];
            #pragma unroll
            for (int i = 0; i < 4; i++)
                #pragma unroll
                for (int j = 0; j < 4; j++)
                    acc[i][j] = fmaf(a[i], b[j], acc[i][j]);
        }
        __syncthreads();
    }

    #pragma unroll
    for (int i = 0; i < 4; i++) {
        size_t base = ((size_t)bh * SEQ + (m0 + ty * 4 + i)) * DKH;
        #pragma unroll
        for (int j = 0; j < 4; j++)
            g_ctx[base + tx * 4 + j] = acc[i][j];
    }
}

// ---------------------------------------------------------------------------
// Output projection: out[m, n] = sum_k ctx_flat[m, k] * Wo[k, n] + bo[n]
// ctx is stored head-split, gathered during the A-tile load.
// ---------------------------------------------------------------------------
__global__ __launch_bounds__(256) void outproj_kernel(
    const float* __restrict__ Wo, const float* __restrict__ bo,
    float* __restrict__ out)
{
    __shared__ float As[16][64];   // [k][m]
    __shared__ float Bs[16][64];   // [k][n]

    const int n0 = blockIdx.x * 64;
    const int m0 = blockIdx.y * 64;
    const int tid = threadIdx.x;
    const int tx = tid & 15, ty = tid >> 4;

    float acc[4][4] = {};

    for (int k0 = 0; k0 < DMODEL; k0 += 16) {
        {   // A tile gather from head-split g_ctx
            int row = tid >> 2;                 // 0..63 within m-tile
            int kq  = (tid & 3) * 4;            // 0..12 within k-tile
            int m = m0 + row;
            int b = m / SEQ, s = m % SEQ;
            int kcol = k0 + kq;
            int h = kcol / DKH, dk = kcol % DKH;   // 16 | 64 so h constant over 4
            float4 a = *(const float4*)
                &g_ctx[((size_t)(b * NHEAD + h) * SEQ + s) * DKH + dk];
            As[kq + 0][row] = a.x; As[kq + 1][row] = a.y;
            As[kq + 2][row] = a.z; As[kq + 3][row] = a.w;
        }
        {
            int row = tid >> 4;
            int nq  = (tid & 15) * 4;
            *(float4*)&Bs[row][nq] =
                *(const float4*)&Wo[(size_t)(k0 + row) * DMODEL + n0 + nq];
        }
        __syncthreads();
        #pragma unroll
        for (int k = 0; k < 16; k++) {
            float a[4], b[4];
            #pragma unroll
            for (int i = 0; i < 4; i++) a[i] = As[k][ty * 4 + i];
            #pragma unroll
            for (int j = 0; j < 4; j++) b[j] = Bs[k][tx * 4 + j];
            #pragma unroll
            for (int i = 0; i < 4; i++)
                #pragma unroll
                for (int j = 0; j < 4; j++)
                    acc[i][j] = fmaf(a[i], b[j], acc[i][j]);
        }
        __syncthreads();
    }

    #pragma unroll
    for (int i = 0; i < 4; i++) {
        int m = m0 + ty * 4 + i;
        #pragma unroll
        for (int j = 0; j < 4; j++) {
            int n = n0 + tx * 4 + j;
            out[(size_t)m * DMODEL + n] = acc[i][j] + bo[n];
        }
    }
}

// ---------------------------------------------------------------------------
extern "C" void kernel_launch(void* const* d_in, const int* in_sizes, int n_in,
                              void* d_out, int out_size)
{
    const float *q, *k, *v, *Wq, *bq, *Wk, *bk, *Wv, *bv, *Wo, *bo;

    if (in_sizes[0] == BATCH * SEQ * DMODEL) {
        // dict-insertion order (confirmed by round-3/4 evidence)
        q  = (const float*)d_in[0];
        k  = (const float*)d_in[1];
        v  = (const float*)d_in[2];
        Wq = (const float*)d_in[3];
        bq = (const float*)d_in[4];
        Wk = (const float*)d_in[5];
        bk = (const float*)d_in[6];
        Wv = (const float*)d_in[7];
        bv = (const float*)d_in[8];
        Wo = (const float*)d_in[9];
        bo = (const float*)d_in[10];
    } else {
        // sorted-key (pytree) order fallback: Wk Wo Wq Wv bk bo bq bv k q v
        Wk = (const float*)d_in[0];
        Wo = (const float*)d_in[1];
        Wq = (const float*)d_in[2];
        Wv = (const float*)d_in[3];
        bk = (const float*)d_in[4];
        bo = (const float*)d_in[5];
        bq = (const float*)d_in[6];
        bv = (const float*)d_in[7];
        k  = (const float*)d_in[8];
        q  = (const float*)d_in[9];
        v  = (const float*)d_in[10];
    }

    float* out  = (float*)d_out;                              // [B, S, DM]
    float* attn = out + (size_t)BATCH * SEQ * DMODEL;         // [B, H, S, S]

    dim3 blk(256);
    dim3 gProj(DMODEL / 64, MROWS / 64);                      // 16 x 64
    proj_kernel<<<gProj, blk>>>(q, Wq, bq, 0);                // -> g_Qh
    proj_kernel<<<gProj, blk>>>(k, Wk, bk, 1);                // -> g_Kh
    proj_kernel<<<gProj, blk>>>(v, Wv, bv, 2);                // -> g_Vh

    dim3 gScores(SEQ / 64, SEQ / 64, BATCH * NHEAD);          // 32 x 32 x 32
    scores_kernel<<<gScores, blk>>>(attn);

    softmax_kernel<<<BATCH * NHEAD * SEQ, blk>>>(attn);       // 65536 rows

    dim3 gCtx(SEQ / 64, BATCH * NHEAD);                       // 32 x 32
    ctx_kernel<<<gCtx, blk>>>(attn);

    outproj_kernel<<<gProj, blk>>>(Wo, bo, out);
}

// round 11
// speedup vs baseline: 1.0036x; 1.0036x over previous
#include <cuda_runtime.h>
#include <math.h>

#define BATCH  2
#define SEQ    2048
#define DMODEL 1024
#define NHEAD  16
#define DKH    64
#define MROWS  (BATCH * SEQ)          // 4096

// Scratch (static device globals: allocation-free, allowed by harness rules).
// NOTE: these must only ever be referenced from DEVICE code. Passing them as
// kernel arguments from host code yields the host shadow address (silently
// writable on GB300 via ATS!) — that was the round-3/4 bug.
__device__ float g_Qh[BATCH * NHEAD * SEQ * DKH];
__device__ float g_Kh[BATCH * NHEAD * SEQ * DKH];
__device__ float g_Vh[BATCH * NHEAD * SEQ * DKH];
__device__ float g_ctx[BATCH * NHEAD * SEQ * DKH];

// ---------------------------------------------------------------------------
// Projection GEMM: out_headsplit[b,h,s,dk] = (X @ W + bias)
// X: [MROWS, DMODEL] row-major. W: [DMODEL, DMODEL]. 64x64 tile, BK=16,
// 256 threads, 4x4 micro-tile per thread. N-tile of 64 == exactly one head.
// dst: 0 -> g_Qh, 1 -> g_Kh, 2 -> g_Vh  (resolved in device code!)
// ---------------------------------------------------------------------------
__global__ __launch_bounds__(256) void proj_kernel(
    const float* __restrict__ X, const float* __restrict__ W,
    const float* __restrict__ bias, int dst)
{
    float* out = (dst == 0) ? g_Qh : (dst == 1) ? g_Kh : g_Vh;

    __shared__ float As[16][64];   // [k][m]  (transposed A tile)
    __shared__ float Bs[16][64];   // [k][n]

    const int n0 = blockIdx.x * 64;
    const int m0 = blockIdx.y * 64;
    const int tid = threadIdx.x;
    const int tx = tid & 15, ty = tid >> 4;

    float acc[4][4] = {};

    for (int k0 = 0; k0 < DMODEL; k0 += 16) {
        {   // A tile: 64 rows x 16 k, one float4 per thread
            int row = tid >> 2;
            int kq  = (tid & 3) * 4;
            float4 a = *(const float4*)&X[(size_t)(m0 + row) * DMODEL + k0 + kq];
            As[kq + 0][row] = a.x; As[kq + 1][row] = a.y;
            As[kq + 2][row] = a.z; As[kq + 3][row] = a.w;
        }
        {   // B tile: 16 rows x 64 n, one float4 per thread
            int row = tid >> 4;
            int nq  = (tid & 15) * 4;
            *(float4*)&Bs[row][nq] =
                *(const float4*)&W[(size_t)(k0 + row) * DMODEL + n0 + nq];
        }
        __syncthreads();
        #pragma unroll
        for (int k = 0; k < 16; k++) {
            float a[4], b[4];
            #pragma unroll
            for (int i = 0; i < 4; i++) a[i] = As[k][ty * 4 + i];
            #pragma unroll
            for (int j = 0; j < 4; j++) b[j] = Bs[k][tx * 4 + j];
            #pragma unroll
            for (int i = 0; i < 4; i++)
                #pragma unroll
                for (int j = 0; j < 4; j++)
                    acc[i][j] = fmaf(a[i], b[j], acc[i][j]);
        }
        __syncthreads();
    }

    const int h = n0 / DKH;   // one head per N-tile
    #pragma unroll
    for (int i = 0; i < 4; i++) {
        int m = m0 + ty * 4 + i;
        int b = m / SEQ, s = m % SEQ;
        size_t base = ((size_t)(b * NHEAD + h) * SEQ + s) * DKH;
        #pragma unroll
        for (int j = 0; j < 4; j++) {
            int dk = tx * 4 + j;
            out[base + dk] = acc[i][j] + bias[n0 + dk];
        }
    }
}

// ---------------------------------------------------------------------------
// Scores: attn[bh, i, j] = (Qh[bh,i,:] . Kh[bh,j,:]) / 8
// Per block: 64x64 output tile, full K=64 reduction in one shot.
// ---------------------------------------------------------------------------
__global__ __launch_bounds__(256) void scores_kernel(float* __restrict__ attn)
{
    __shared__ float Qs[64][65];   // [m][k], padded
    __shared__ float Ks[64][65];   // [n][k], padded

    const int bh = blockIdx.z;
    const int n0 = blockIdx.x * 64;
    const int m0 = blockIdx.y * 64;
    const float* Q  = g_Qh + (size_t)bh * SEQ * DKH;
    const float* Kp = g_Kh + (size_t)bh * SEQ * DKH;
    const int tid = threadIdx.x;

    #pragma unroll
    for (int r = 0; r < 4; r++) {
        int row = (tid >> 4) + r * 16;       // 0..63
        int kq  = (tid & 15) * 4;
        float4 qv = *(const float4*)&Q [(size_t)(m0 + row) * DKH + kq];
        float4 kv = *(const float4*)&Kp[(size_t)(n0 + row) * DKH + kq];
        Qs[row][kq + 0] = qv.x; Qs[row][kq + 1] = qv.y;
        Qs[row][kq + 2] = qv.z; Qs[row][kq + 3] = qv.w;
        Ks[row][kq + 0] = kv.x; Ks[row][kq + 1] = kv.y;
        Ks[row][kq + 2] = kv.z; Ks[row][kq + 3] = kv.w;
    }
    __syncthreads();

    const int tx = tid & 15, ty = tid >> 4;
    float acc[4][4] = {};
    #pragma unroll
    for (int k = 0; k < 64; k++) {
        float a[4], b[4];
        #pragma unroll
        for (int i = 0; i < 4; i++) a[i] = Qs[ty * 4 + i][k];
        #pragma unroll
        for (int j = 0; j < 4; j++) b[j] = Ks[tx * 4 + j][k];
        #pragma unroll
        for (int i = 0; i < 4; i++)
            #pragma unroll
            for (int j = 0; j < 4; j++)
                acc[i][j] = fmaf(a[i], b[j], acc[i][j]);
    }

    #pragma unroll
    for (int i = 0; i < 4; i++) {
        size_t rowbase = ((size_t)bh * SEQ + (m0 + ty * 4 + i)) * SEQ + n0;
        #pragma unroll
        for (int j = 0; j < 4; j++)
            attn[rowbase + tx * 4 + j] = acc[i][j] * 0.125f;
    }
}

// ---------------------------------------------------------------------------
// Row softmax over 2048 elements, one block (256 threads) per row, in place.
// ---------------------------------------------------------------------------
__global__ __launch_bounds__(256) void softmax_kernel(float* __restrict__ attn)
{
    __shared__ float red[8];
    float* p = attn + (size_t)blockIdx.x * SEQ;
    const int tid  = threadIdx.x;
    const int lane = tid & 31, warp = tid >> 5;

    float4 v0 = ((const float4*)p)[tid];
    float4 v1 = ((const float4*)p)[tid + 256];

    float mx = fmaxf(fmaxf(fmaxf(v0.x, v0.y), fmaxf(v0.z, v0.w)),
                     fmaxf(fmaxf(v1.x, v1.y), fmaxf(v1.z, v1.w)));
    #pragma unroll
    for (int o = 16; o; o >>= 1) mx = fmaxf(mx, __shfl_xor_sync(0xffffffffu, mx, o));
    if (lane == 0) red[warp] = mx;
    __syncthreads();
    mx = red[0];
    #pragma unroll
    for (int w = 1; w < 8; w++) mx = fmaxf(mx, red[w]);
    __syncthreads();

    v0.x = __expf(v0.x - mx); v0.y = __expf(v0.y - mx);
    v0.z = __expf(v0.z - mx); v0.w = __expf(v0.w - mx);
    v1.x = __expf(v1.x - mx); v1.y = __expf(v1.y - mx);
    v1.z = __expf(v1.z - mx); v1.w = __expf(v1.w - mx);

    float sum = (v0.x + v0.y + v0.z + v0.w) + (v1.x + v1.y + v1.z + v1.w);
    #pragma unroll
    for (int o = 16; o; o >>= 1) sum += __shfl_xor_sync(0xffffffffu, sum, o);
    if (lane == 0) red[warp] = sum;
    __syncthreads();
    sum = red[0];
    #pragma unroll
    for (int w = 1; w < 8; w++) sum += red[w];

    float inv = 1.0f / sum;
    v0.x *= inv; v0.y *= inv; v0.z *= inv; v0.w *= inv;
    v1.x *= inv; v1.y *= inv; v1.z *= inv; v1.w *= inv;
    ((float4*)p)[tid]       = v0;
    ((float4*)p)[tid + 256] = v1;
}

// ---------------------------------------------------------------------------
// Context: g_ctx[bh, m, n] = sum_k attn[bh, m, k] * Vh[bh, k, n]
// M=2048, K=2048, N=64 per (b,h). 64x64 tile (full N), BK=32.
// ---------------------------------------------------------------------------
__global__ __launch_bounds__(256) void ctx_kernel(const float* __restrict__ attn)
{
    __shared__ float As[64][33];   // [m][k], padded
    __shared__ float Bs[32][64];   // [k][n]

    const int bh = blockIdx.y;
    const int m0 = blockIdx.x * 64;
    const float* V = g_Vh + (size_t)bh * SEQ * DKH;
    const float* A = attn + ((size_t)bh * SEQ + m0) * SEQ;
    const int tid = threadIdx.x;
    const int tx = tid & 15, ty = tid >> 4;

    float acc[4][4] = {};

    for (int k0 = 0; k0 < SEQ; k0 += 32) {
        #pragma unroll
        for (int r = 0; r < 2; r++) {      // A tile: 64x32, 2 float4 / thread
            int row = (tid >> 3) + r * 32;
            int kq  = (tid & 7) * 4;
            float4 a = *(const float4*)&A[(size_t)row * SEQ + k0 + kq];
            As[row][kq + 0] = a.x; As[row][kq + 1] = a.y;
            As[row][kq + 2] = a.z; As[row][kq + 3] = a.w;
        }
        #pragma unroll
        for (int r = 0; r < 2; r++) {      // B tile: 32x64, 2 float4 / thread
            int row = (tid >> 4) + r * 16;
            int nq  = (tid & 15) * 4;
            *(float4*)&Bs[row][nq] =
                *(const float4*)&V[(size_t)(k0 + row) * DKH + nq];
        }
        __syncthreads();
        #pragma unroll
        for (int k = 0; k < 32; k++) {
            float a[4], b[4];
            #pragma unroll
            for (int i = 0; i < 4; i++) a[i] = As[ty * 4 + i][k];
            #pragma unroll
            for (int j = 0; j < 4; j++) b[j] = Bs[k][tx * 4 + j];
            #pragma unroll
            for (int i = 0; i < 4; i++)
                #pragma unroll
                for (int j = 0; j < 4; j++)
                    acc[i][j] = fmaf(a[i], b[j], acc[i][j]);
        }
        __syncthreads();
    }

    #pragma unroll
    for (int i = 0; i < 4; i++) {
        size_t base = ((size_t)bh * SEQ + (m0 + ty * 4 + i)) * DKH;
        #pragma unroll
        for (int j = 0; j < 4; j++)
            g_ctx[base + tx * 4 + j] = acc[i][j];
    }
}

// ---------------------------------------------------------------------------
// Output projection: out[m, n] = sum_k ctx_flat[m, k] * Wo[k, n] + bo[n]
// ctx is stored head-split, gathered during the A-tile load.
// ---------------------------------------------------------------------------
__global__ __launch_bounds__(256) void outproj_kernel(
    const float* __restrict__ Wo, const float* __restrict__ bo,
    float* __restrict__ out)
{
    __shared__ float As[16][64];   // [k][m]
    __shared__ float Bs[16][64];   // [k][n]

    const int n0 = blockIdx.x * 64;
    const int m0 = blockIdx.y * 64;
    const int tid = threadIdx.x;
    const int tx = tid & 15, ty = tid >> 4;

    float acc[4][4] = {};

    for (int k0 = 0; k0 < DMODEL; k0 += 16) {
        {   // A tile gather from head-split g_ctx
            int row = tid >> 2;                 // 0..63 within m-tile
            int kq  = (tid & 3) * 4;            // 0..12 within k-tile
            int m = m0 + row;
            int b = m / SEQ, s = m % SEQ;
            int kcol = k0 + kq;
            int h = kcol / DKH, dk = kcol % DKH;   // 16 | 64 so h constant over 4
            float4 a = *(const float4*)
                &g_ctx[((size_t)(b * NHEAD + h) * SEQ + s) * DKH + dk];
            As[kq + 0][row] = a.x; As[kq + 1][row] = a.y;
            As[kq + 2][row] = a.z; As[kq + 3][row] = a.w;
        }
        {
            int row = tid >> 4;
            int nq  = (tid & 15) * 4;
            *(float4*)&Bs[row][nq] =
                *(const float4*)&Wo[(size_t)(k0 + row) * DMODEL + n0 + nq];
        }
        __syncthreads();
        #pragma unroll
        for (int k = 0; k < 16; k++) {
            float a[4], b[4];
            #pragma unroll
            for (int i = 0; i < 4; i++) a[i] = As[k][ty * 4 + i];
            #pragma unroll
            for (int j = 0; j < 4; j++) b[j] = Bs[k][tx * 4 + j];
            #pragma unroll
            for (int i = 0; i < 4; i++)
                #pragma unroll
                for (int j = 0; j < 4; j++)
                    acc[i][j] = fmaf(a[i], b[j], acc[i][j]);
        }
        __syncthreads();
    }

    #pragma unroll
    for (int i = 0; i < 4; i++) {
        int m = m0 + ty * 4 + i;
        #pragma unroll
        for (int j = 0; j < 4; j++) {
            int n = n0 + tx * 4 + j;
            out[(size_t)m * DMODEL + n] = acc[i][j] + bo[n];
        }
    }
}

// ---------------------------------------------------------------------------
extern "C" void kernel_launch(void* const* d_in, const int* in_sizes, int n_in,
                              void* d_out, int out_size)
{
    const float *q, *k, *v, *Wq, *bq, *Wk, *bk, *Wv, *bv, *Wo, *bo;

    if (in_sizes[0] == BATCH * SEQ * DMODEL) {
        // dict-insertion order (confirmed by round-3/4 evidence)
        q  = (const float*)d_in[0];
        k  = (const float*)d_in[1];
        v  = (const float*)d_in[2];
        Wq = (const float*)d_in[3];
        bq = (const float*)d_in[4];
        Wk = (const float*)d_in[5];
        bk = (const float*)d_in[6];
        Wv = (const float*)d_in[7];
        bv = (const float*)d_in[8];
        Wo = (const float*)d_in[9];
        bo = (const float*)d_in[10];
    } else {
        // sorted-key (pytree) order fallback: Wk Wo Wq Wv bk bo bq bv k q v
        Wk = (const float*)d_in[0];
        Wo = (const float*)d_in[1];
        Wq = (const float*)d_in[2];
        Wv = (const float*)d_in[3];
        bk = (const float*)d_in[4];
        bo = (const float*)d_in[5];
        bq = (const float*)d_in[6];
        bv = (const float*)d_in[7];
        k  = (const float*)d_in[8];
        q  = (const float*)d_in[9];
        v  = (const float*)d_in[10];
    }

    float* out  = (float*)d_out;                              // [B, S, DM]
    float* attn = out + (size_t)BATCH * SEQ * DMODEL;         // [B, H, S, S]

    dim3 blk(256);
    dim3 gProj(DMODEL / 64, MROWS / 64);                      // 16 x 64
    proj_kernel<<<gProj, blk>>>(q, Wq, bq, 0);                // -> g_Qh
    proj_kernel<<<gProj, blk>>>(k, Wk, bk, 1);                // -> g_Kh
    proj_kernel<<<gProj, blk>>>(v, Wv, bv, 2);                // -> g_Vh

    dim3 gScores(SEQ / 64, SEQ / 64, BATCH * NHEAD);          // 32 x 32 x 32
    scores_kernel<<<gScores, blk>>>(attn);

    softmax_kernel<<<BATCH * NHEAD * SEQ, blk>>>(attn);       // 65536 rows

    dim3 gCtx(SEQ / 64, BATCH * NHEAD);                       // 32 x 32
    ctx_kernel<<<gCtx, blk>>>(attn);

    outproj_kernel<<<gProj, blk>>>(Wo, bo, out);
}